// round 17
// baseline (speedup 1.0000x reference)
#include <cuda_runtime.h>
#include <cuda_bf16.h>

#define BATCH 4
#define NP    8192
#define NQ    2048
#define CF    64
#define CT    64
#define KS    32
#define R2    0.04f
#define OUTC  (3 + CF)        // 67 channels in grouped_features
#define P1N   2048            // phase-1 scan length

__device__ uint2 g_idx16_v[BATCH * NQ * KS / 4];   // ushort idx, 4 per uint2
__device__ int   g_wl_n;                           // worklist counter
__device__ int   g_wl_q[BATCH * NQ];               // global query id
__device__ int   g_wl_c[BATCH * NQ];               // partial count
__device__ int   g_wl_slots[BATCH * NQ * KS];      // partial slots

// Phase 1: first 2048 points in 24KB smem. 512 blocks x 512 thr (16 warps =
// 16 queries), ~4 blocks/SM. Early exit; unsatisfied queries -> worklist.
__global__ __launch_bounds__(512) void qg_bq_phase1_kernel(
    const float* __restrict__ coords,
    const float* __restrict__ queries,
    float* __restrict__ out)
{
    __shared__ float sxyz[3 * P1N];    // 24KB
    __shared__ int   slots_s[16][KS];

    int tid  = threadIdx.x;
    int lane = tid & 31;
    int w    = tid >> 5;
    int b    = blockIdx.x >> 7;        // 128 blocks per batch
    int blk  = blockIdx.x & 127;

    const float* cb = coords + (size_t)b * NP * 3;
    #pragma unroll
    for (int j = 0; j < (P1N * 3) / 512; ++j) {
        int i = tid + j * 512;
        float v = cb[i];
        int p = i / 3, d = i - 3 * p;
        sxyz[d * P1N + p] = v;
    }
    __syncthreads();

    float* sx = sxyz;
    float* sy = sxyz + P1N;
    float* sz = sxyz + 2 * P1N;
    int* slots = slots_s[w];
    unsigned lt = (1u << lane) - 1u;
    const size_t stride = (size_t)NQ * KS;

    int q = blk * 16 + w;
    int g = b * NQ + q;
    const float* qp = queries + (size_t)g * 3;
    float qx = qp[0], qy = qp[1], qz = qp[2];

    int count = 0;
    for (int base = 0; base < P1N; base += 64) {
        int i0 = base + lane, i1 = base + 32 + lane;
        float x0 = sx[i0], y0 = sy[i0], z0 = sz[i0];
        float x1 = sx[i1], y1 = sy[i1], z1 = sz[i1];
        // Match XLA rounding exactly: no FMA contraction.
        float dx0 = __fadd_rn(qx, -x0), dy0 = __fadd_rn(qy, -y0), dz0 = __fadd_rn(qz, -z0);
        float d20 = __fadd_rn(__fadd_rn(__fmul_rn(dx0, dx0), __fmul_rn(dy0, dy0)),
                              __fmul_rn(dz0, dz0));
        float dx1 = __fadd_rn(qx, -x1), dy1 = __fadd_rn(qy, -y1), dz1 = __fadd_rn(qz, -z1);
        float d21 = __fadd_rn(__fadd_rn(__fmul_rn(dx1, dx1), __fmul_rn(dy1, dy1)),
                              __fmul_rn(dz1, dz1));
        bool in0 = d20 < R2;
        bool in1 = d21 < R2;
        unsigned m0 = __ballot_sync(0xffffffffu, in0);
        unsigned m1 = __ballot_sync(0xffffffffu, in1);
        if (in0) {
            int s = count + __popc(m0 & lt);
            if (s < KS) slots[s] = i0;
        }
        int c1 = count + __popc(m0);
        if (in1) {
            int s = c1 + __popc(m1 & lt);
            if (s < KS) slots[s] = i1;
        }
        count = c1 + __popc(m1);
        if (count >= KS) break;
    }
    __syncwarp();

    if (count >= KS) {
        int my = slots[lane];
        ((unsigned short*)g_idx16_v)[(size_t)g * KS + lane] = (unsigned short)my;
        size_t ob0 = (size_t)b * OUTC * stride + (size_t)q * KS + lane;
        out[ob0]              = sx[my] - qx;
        out[ob0 + stride]     = sy[my] - qy;
        out[ob0 + 2 * stride] = sz[my] - qz;
    } else {
        int e;
        if (lane == 0) {
            e = atomicAdd(&g_wl_n, 1);
            g_wl_q[e] = g;
            g_wl_c[e] = count;
        }
        e = __shfl_sync(0xffffffffu, e, 0);
        g_wl_slots[(size_t)e * KS + lane] = (lane < count) ? slots[lane] : 0;
    }
}

// Phase 2: finish the tail queries (points 2048..8192 from L2 coords).
// 256 blocks x 256 thr = 2048 warps, strided over worklist entries.
__global__ __launch_bounds__(256) void qg_bq_phase2_kernel(
    const float* __restrict__ coords,
    const float* __restrict__ queries,
    float* __restrict__ out)
{
    __shared__ int slots_s[8][KS];

    int lane = threadIdx.x & 31;
    int w    = threadIdx.x >> 5;
    int gw   = blockIdx.x * 8 + w;
    const int nwarps = 256 * 8;
    unsigned lt = (1u << lane) - 1u;
    const size_t stride = (size_t)NQ * KS;
    int* slots = slots_s[w];

    int nwl = g_wl_n;
    for (int e = gw; e < nwl; e += nwarps) {
        int g = g_wl_q[e];
        int count = g_wl_c[e];
        slots[lane] = g_wl_slots[(size_t)e * KS + lane];
        __syncwarp();

        int b = g >> 11;
        int q = g & (NQ - 1);
        const float* cb = coords + (size_t)b * NP * 3;
        const float* qp = queries + (size_t)g * 3;
        float qx = qp[0], qy = qp[1], qz = qp[2];

        for (int base = P1N; base < NP; base += 64) {
            int i0 = base + lane, i1 = base + 32 + lane;
            float x0 = cb[i0 * 3], y0 = cb[i0 * 3 + 1], z0 = cb[i0 * 3 + 2];
            float x1 = cb[i1 * 3], y1 = cb[i1 * 3 + 1], z1 = cb[i1 * 3 + 2];
            // Match XLA rounding exactly: no FMA contraction.
            float dx0 = __fadd_rn(qx, -x0), dy0 = __fadd_rn(qy, -y0), dz0 = __fadd_rn(qz, -z0);
            float d20 = __fadd_rn(__fadd_rn(__fmul_rn(dx0, dx0), __fmul_rn(dy0, dy0)),
                                  __fmul_rn(dz0, dz0));
            float dx1 = __fadd_rn(qx, -x1), dy1 = __fadd_rn(qy, -y1), dz1 = __fadd_rn(qz, -z1);
            float d21 = __fadd_rn(__fadd_rn(__fmul_rn(dx1, dx1), __fmul_rn(dy1, dy1)),
                                  __fmul_rn(dz1, dz1));
            bool in0 = d20 < R2;
            bool in1 = d21 < R2;
            unsigned m0 = __ballot_sync(0xffffffffu, in0);
            unsigned m1 = __ballot_sync(0xffffffffu, in1);
            if (count < KS) {
                if (in0) {
                    int s = count + __popc(m0 & lt);
                    if (s < KS) slots[s] = i0;
                }
                int c1 = count + __popc(m0);
                if (in1) {
                    int s = c1 + __popc(m1 & lt);
                    if (s < KS) slots[s] = i1;
                }
            }
            count += __popc(m0) + __popc(m1);
            if (count >= KS) break;
        }
        __syncwarp();

        int cnt   = count < KS ? count : KS;
        int first = (count > 0) ? slots[0] : 0;
        int my    = (lane < cnt) ? slots[lane] : first;
        ((unsigned short*)g_idx16_v)[(size_t)g * KS + lane] = (unsigned short)my;

        size_t ob0 = (size_t)b * OUTC * stride + (size_t)q * KS + lane;
        out[ob0]              = cb[my * 3 + 0] - qx;
        out[ob0 + stride]     = cb[my * 3 + 1] - qy;
        out[ob0 + 2 * stride] = cb[my * 3 + 2] - qz;
        __syncwarp();
    }
}

// Gather (exact R13 best config): block per (batch, channel-pair, query-chunk)
// = 512 blocks, 256 threads, 64KB smem, ushort idx, 4 prefetched streams.
__global__ __launch_bounds__(256) void qg_gather_kernel(
    const float* __restrict__ feats,
    const float* __restrict__ temb,
    float* __restrict__ out)
{
    extern __shared__ float2 rows[];    // [NP] interleaved channel pair (64KB)

    int tid   = threadIdx.x;
    int bc    = blockIdx.x;             // 0..511
    int chunk = bc & 1;
    int pair  = (bc >> 1) & 63;
    int b     = bc >> 7;
    int cc    = pair * 2;               // 0..126
    int which = cc >> 6;
    int ch    = cc & 63;

    const float* s0 = (which ? temb : feats) + ((size_t)b * 64 + ch) * NP;
    for (int p = tid; p < NP; p += 256)
        rows[p] = make_float2(s0[p], s0[NP + p]);
    __syncthreads();

    const size_t stride = (size_t)NQ * KS;
    size_t ob0;
    if (which == 0)
        ob0 = (size_t)b * OUTC * stride + (size_t)(3 + ch) * stride;
    else
        ob0 = (size_t)BATCH * OUTC * stride + (size_t)b * CT * stride + (size_t)ch * stride;
    size_t ob1 = ob0 + stride;

    const uint2* idxp = g_idx16_v + (size_t)b * (NQ * KS / 4) + chunk * 8192;

    uint2 cur0 = idxp[0 * 2048 + tid];
    uint2 cur1 = idxp[1 * 2048 + tid];
    uint2 cur2 = idxp[2 * 2048 + tid];
    uint2 cur3 = idxp[3 * 2048 + tid];

    #pragma unroll
    for (int it = 0; it < 8; ++it) {
        uint2 n0, n1, n2, n3;
        if (it < 7) {
            int o = (it + 1) * 256 + tid;
            n0 = idxp[0 * 2048 + o];
            n1 = idxp[1 * 2048 + o];
            n2 = idxp[2 * 2048 + o];
            n3 = idxp[3 * 2048 + o];
        }
        #pragma unroll
        for (int s = 0; s < 4; ++s) {
            uint2 u = (s == 0) ? cur0 : (s == 1) ? cur1 : (s == 2) ? cur2 : cur3;
            int ge = chunk * 8192 + s * 2048 + it * 256 + tid;   // group id in batch
            float2 f0 = rows[u.x & 0xffff];
            float2 f1 = rows[u.x >> 16];
            float2 f2 = rows[u.y & 0xffff];
            float2 f3 = rows[u.y >> 16];
            size_t pe = (size_t)ge * 4;
            *(float4*)(out + ob0 + pe) = make_float4(f0.x, f1.x, f2.x, f3.x);
            *(float4*)(out + ob1 + pe) = make_float4(f0.y, f1.y, f2.y, f3.y);
        }
        cur0 = n0; cur1 = n1; cur2 = n2; cur3 = n3;
    }
}

extern "C" void kernel_launch(void* const* d_in, const int* in_sizes, int n_in,
                              void* d_out, int out_size) {
    const float* coords  = (const float*)d_in[0];  // [B,Np,3]
    const float* feats   = (const float*)d_in[1];  // [B,C,Np]
    const float* temb    = (const float*)d_in[2];  // [B,Ct,Np]
    const float* queries = (const float*)d_in[3];  // [B,Nq,3]
    float* out = (float*)d_out;

    const int gt_smem = NP * (int)sizeof(float2);       // 64KB
    cudaFuncSetAttribute(qg_gather_kernel,
                         cudaFuncAttributeMaxDynamicSharedMemorySize, gt_smem);

    void* wl_ptr = nullptr;
    cudaGetSymbolAddress(&wl_ptr, g_wl_n);
    cudaMemsetAsync(wl_ptr, 0, sizeof(int));            // graph-capturable node

    qg_bq_phase1_kernel<<<BATCH * 128, 512>>>(coords, queries, out);
    qg_bq_phase2_kernel<<<256, 256>>>(coords, queries, out);
    qg_gather_kernel<<<512, 256, gt_smem>>>(feats, temb, out);
}